// round 9
// baseline (speedup 1.0000x reference)
#include <cuda_runtime.h>
#include <cuda_fp16.h>

#define N_POINTS 1000000
#define GRID_D   128
#define CH       32
#define CHP      16                            // channels per pass
#define NVOX     (GRID_D * GRID_D * GRID_D)    // 2,097,152

// Two 64MB fp16 half-grids, voxel-major: [pass][vox][16ch].
__device__ __half g_feat_h[2 * (size_t)NVOX * CHP];

// ---------------------------------------------------------------------------
// Transpose one 16-channel half: (16ch, V) fp32 -> (V, 16ch) fp16.
// ---------------------------------------------------------------------------
__global__ __launch_bounds__(256) void transpose_half(const float* __restrict__ feature,
                                                      int pass) {
    __shared__ float tile[CHP * 256];
    const int t  = threadIdx.x;
    const int s0 = blockIdx.x * 256;
    const int ch_base = pass * CHP;
    __half* dst = g_feat_h + (size_t)pass * NVOX * CHP;

    float4 v[4];
    #pragma unroll
    for (int r = 0; r < 4; ++r) {
        const int i  = r * 256 + t;            // 0..1023 float4 slots
        const int ch = i >> 6;                 // 0..15
        const int c4 = i & 63;
        v[r] = __ldcs(reinterpret_cast<const float4*>(
                  &feature[(size_t)(ch_base + ch) * NVOX + s0 + c4 * 4]));
    }
    #pragma unroll
    for (int r = 0; r < 4; ++r) {
        const int i   = r * 256 + t;
        const int ch  = i >> 6;
        const int c4  = i & 63;
        const int col = (c4 * 4) ^ (((ch >> 3) & 1) * 16);
        *reinterpret_cast<float4*>(&tile[ch * 256 + col]) = v[r];
    }
    __syncthreads();

    #pragma unroll
    for (int r = 0; r < 2; ++r) {
        const int i   = r * 256 + t;           // 0..511 output uint4 slots
        const int vox = i >> 1;                // 0..255
        const int oct = i & 1;                 // which 8-channel octet
        half2 h[4];
        #pragma unroll
        for (int kk = 0; kk < 4; ++kk) {
            const int ch0 = oct * 8 + kk * 2;
            const int ch1 = ch0 + 1;
            const int s   = ((ch0 >> 3) & 1) * 16;   // same for ch1
            const float a = tile[ch0 * 256 + (vox ^ s)];
            const float b = tile[ch1 * 256 + (vox ^ s)];
            h[kk] = __floats2half2_rn(a, b);
        }
        uint4 o;
        o.x = *reinterpret_cast<unsigned*>(&h[0]);
        o.y = *reinterpret_cast<unsigned*>(&h[1]);
        o.z = *reinterpret_cast<unsigned*>(&h[2]);
        o.w = *reinterpret_cast<unsigned*>(&h[3]);
        *reinterpret_cast<uint4*>(&dst[(size_t)(s0 + vox) * CHP + oct * 8]) = o;
    }
}

// ---------------------------------------------------------------------------
// Gather one 16-channel half. 2 lanes/point; each lane owns 8 channels
// (16B uint4 per corner). 8 corner loads batched -> MLP=8.
// ---------------------------------------------------------------------------
__global__ __launch_bounds__(256) void gather_half(const float* __restrict__ x,
                                                   float* __restrict__ out,
                                                   int pass) {
    const int tid = blockIdx.x * blockDim.x + threadIdx.x;
    const int p   = tid >> 1;                  // point index
    const int q   = tid & 1;                   // octet within this half
    if (p >= N_POINTS) return;
    const __half* grid = g_feat_h + (size_t)pass * NVOX * CHP;

    const float px = __ldg(&x[3 * p + 0]);
    const float py = __ldg(&x[3 * p + 1]);
    const float pz = __ldg(&x[3 * p + 2]);

    // fx = x*6.4 + 63.5  (LO=-10, HI=10, W=128)
    const float fx = fmaf(px, 6.4f, 63.5f);
    const float fy = fmaf(py, 6.4f, 63.5f);
    const float fz = fmaf(pz, 6.4f, 63.5f);

    const float x0f = floorf(fx), y0f = floorf(fy), z0f = floorf(fz);
    const float wx = fx - x0f, wy = fy - y0f, wz = fz - z0f;
    const int x0 = (int)x0f, y0 = (int)y0f, z0 = (int)z0f;

    float  w[8];
    size_t idx[8];
    #pragma unroll
    for (int c = 0; c < 8; ++c) {
        const int dx = c & 1, dy = (c >> 1) & 1, dz = (c >> 2) & 1;
        const int xi = x0 + dx, yi = y0 + dy, zi = z0 + dz;
        const bool vld = (xi >= 0) && (xi < GRID_D) &&
                         (yi >= 0) && (yi < GRID_D) &&
                         (zi >= 0) && (zi < GRID_D);
        const int cx = min(max(xi, 0), GRID_D - 1);
        const int cy = min(max(yi, 0), GRID_D - 1);
        const int cz = min(max(zi, 0), GRID_D - 1);
        const float wxt = dx ? wx : 1.0f - wx;
        const float wyt = dy ? wy : 1.0f - wy;
        const float wzt = dz ? wz : 1.0f - wz;
        w[c]   = vld ? (wxt * wyt * wzt) : 0.0f;
        idx[c] = ((size_t)((cz * GRID_D + cy) * GRID_D + cx)) * CHP + q * 8;
    }

    uint4 cv[8];
    #pragma unroll
    for (int c = 0; c < 8; ++c)
        cv[c] = *reinterpret_cast<const uint4*>(&grid[idx[c]]);

    float acc[8] = {0.f, 0.f, 0.f, 0.f, 0.f, 0.f, 0.f, 0.f};
    #pragma unroll
    for (int c = 0; c < 8; ++c) {
        const unsigned u[4] = {cv[c].x, cv[c].y, cv[c].z, cv[c].w};
        #pragma unroll
        for (int kk = 0; kk < 4; ++kk) {
            const half2  h2 = *reinterpret_cast<const half2*>(&u[kk]);
            const float2 f2 = __half22float2(h2);
            acc[kk * 2 + 0] = fmaf(w[c], f2.x, acc[kk * 2 + 0]);
            acc[kk * 2 + 1] = fmaf(w[c], f2.y, acc[kk * 2 + 1]);
        }
    }

    float* op = out + (size_t)p * CH + pass * CHP + q * 8;
    __stcs(reinterpret_cast<float4*>(op),     make_float4(acc[0], acc[1], acc[2], acc[3]));
    __stcs(reinterpret_cast<float4*>(op + 4), make_float4(acc[4], acc[5], acc[6], acc[7]));
}

extern "C" void kernel_launch(void* const* d_in, const int* in_sizes, int n_in,
                              void* d_out, int out_size) {
    const float* x       = (const float*)d_in[0];   // (N_POINTS, 3)
    const float* feature = (const float*)d_in[1];   // (32, 128, 128, 128)
    float*       out     = (float*)d_out;           // (N_POINTS, 32)

    // Lazily-created side stream + events (host-side resources only; the
    // per-call WORK is identical every invocation).
    static cudaStream_t s1 = nullptr;
    static cudaEvent_t  ev_fork = nullptr, ev_join = nullptr;
    if (!s1) {
        cudaStreamCreateWithFlags(&s1, cudaStreamNonBlocking);
        cudaEventCreateWithFlags(&ev_fork, cudaEventDisableTiming);
        cudaEventCreateWithFlags(&ev_join, cudaEventDisableTiming);
    }

    const int gblocks = (N_POINTS * 2 + 255) / 256;
    const int tblocks = NVOX / 256;

    // Fork side stream from the (possibly capturing) legacy stream.
    cudaEventRecord(ev_fork, 0);
    cudaStreamWaitEvent(s1, ev_fork, 0);

    // main stream: transpose0 -> gather0
    transpose_half<<<tblocks, 256>>>(feature, 0);
    gather_half<<<gblocks, 256>>>(x, out, 0);

    // side stream: transpose1 (independent of pass 0) overlaps gather0
    transpose_half<<<tblocks, 256, 0, s1>>>(feature, 1);
    cudaEventRecord(ev_join, s1);

    // join, then gather1 on the main stream
    cudaStreamWaitEvent(0, ev_join, 0);
    gather_half<<<gblocks, 256>>>(x, out, 1);
}

// round 10
// speedup vs baseline: 1.2780x; 1.2780x over previous
#include <cuda_runtime.h>
#include <cuda_fp16.h>

#define N_POINTS 1000000
#define GRID_D   128
#define CH       32
#define CHP      16                            // channels per pass
#define NVOX     (GRID_D * GRID_D * GRID_D)    // 2,097,152

// Two 64MB fp16 half-grids, voxel-major: [pass][vox][16ch].
__device__ __half g_feat_h[2 * (size_t)NVOX * CHP];

// ---------------------------------------------------------------------------
// Transpose one 16-channel half: (16ch, V) fp32 -> (V, 16ch) fp16.
// (unchanged from R8 — measured at memory roofline)
// ---------------------------------------------------------------------------
__global__ __launch_bounds__(256) void transpose_half(const float* __restrict__ feature,
                                                      int pass) {
    __shared__ float tile[CHP * 256];
    const int t  = threadIdx.x;
    const int s0 = blockIdx.x * 256;
    const int ch_base = pass * CHP;
    __half* dst = g_feat_h + (size_t)pass * NVOX * CHP;

    float4 v[4];
    #pragma unroll
    for (int r = 0; r < 4; ++r) {
        const int i  = r * 256 + t;
        const int ch = i >> 6;
        const int c4 = i & 63;
        v[r] = __ldcs(reinterpret_cast<const float4*>(
                  &feature[(size_t)(ch_base + ch) * NVOX + s0 + c4 * 4]));
    }
    #pragma unroll
    for (int r = 0; r < 4; ++r) {
        const int i   = r * 256 + t;
        const int ch  = i >> 6;
        const int c4  = i & 63;
        const int col = (c4 * 4) ^ (((ch >> 3) & 1) * 16);
        *reinterpret_cast<float4*>(&tile[ch * 256 + col]) = v[r];
    }
    __syncthreads();

    #pragma unroll
    for (int r = 0; r < 2; ++r) {
        const int i   = r * 256 + t;
        const int vox = i >> 1;
        const int oct = i & 1;
        half2 h[4];
        #pragma unroll
        for (int kk = 0; kk < 4; ++kk) {
            const int ch0 = oct * 8 + kk * 2;
            const int ch1 = ch0 + 1;
            const int s   = ((ch0 >> 3) & 1) * 16;
            const float a = tile[ch0 * 256 + (vox ^ s)];
            const float b = tile[ch1 * 256 + (vox ^ s)];
            h[kk] = __floats2half2_rn(a, b);
        }
        uint4 o;
        o.x = *reinterpret_cast<unsigned*>(&h[0]);
        o.y = *reinterpret_cast<unsigned*>(&h[1]);
        o.z = *reinterpret_cast<unsigned*>(&h[2]);
        o.w = *reinterpret_cast<unsigned*>(&h[3]);
        *reinterpret_cast<uint4*>(&dst[(size_t)(s0 + vox) * CHP + oct * 8]) = o;
    }
}

// ---------------------------------------------------------------------------
// Gather one 16-channel half. 4 lanes/point: q = (xs<<1)|octet.
// Lane loads vox(y,z, x0+xs)*32B + octet*16B -> per (dy,dz) one instruction
// spans the contiguous 64B x-pair: merged wavefronts (~1.25 lines vs 2).
// Partial sums over xs combined via shfl_xor(2); one float4 store per lane.
// ---------------------------------------------------------------------------
__global__ __launch_bounds__(256) void gather_half(const float* __restrict__ x,
                                                   float* __restrict__ out,
                                                   int pass) {
    const int tid = blockIdx.x * blockDim.x + threadIdx.x;
    const int p   = tid >> 2;                  // point index
    const int q   = tid & 3;
    const int oc  = q & 1;                     // channel octet (8 ch)
    const int xs  = q >> 1;                    // which x-corner this lane owns
    if (p >= N_POINTS) return;
    const __half* grid = g_feat_h + (size_t)pass * NVOX * CHP;

    const float px = __ldg(&x[3 * p + 0]);
    const float py = __ldg(&x[3 * p + 1]);
    const float pz = __ldg(&x[3 * p + 2]);

    // fx = x*6.4 + 63.5  (LO=-10, HI=10, W=128)
    const float fx = fmaf(px, 6.4f, 63.5f);
    const float fy = fmaf(py, 6.4f, 63.5f);
    const float fz = fmaf(pz, 6.4f, 63.5f);

    const float x0f = floorf(fx), y0f = floorf(fy), z0f = floorf(fz);
    const float wx = fx - x0f, wy = fy - y0f, wz = fz - z0f;
    const int x0 = (int)x0f, y0 = (int)y0f, z0 = (int)z0f;

    // this lane's x corner (validity folded into the weight)
    const int  xi  = x0 + xs;
    const bool vx  = (xi >= 0) && (xi < GRID_D);
    const int  cx  = min(max(xi, 0), GRID_D - 1);
    const float wxt = (xs ? wx : 1.0f - wx) * (vx ? 1.0f : 0.0f);

    float  w4[4];
    size_t idx4[4];
    #pragma unroll
    for (int c = 0; c < 4; ++c) {
        const int dy = c & 1, dz = c >> 1;
        const int yi = y0 + dy, zi = z0 + dz;
        const bool v = (yi >= 0) && (yi < GRID_D) && (zi >= 0) && (zi < GRID_D);
        const int cy = min(max(yi, 0), GRID_D - 1);
        const int cz = min(max(zi, 0), GRID_D - 1);
        const float wyt = dy ? wy : 1.0f - wy;
        const float wzt = dz ? wz : 1.0f - wz;
        w4[c]   = v ? (wxt * wyt * wzt) : 0.0f;
        idx4[c] = ((size_t)((cz * GRID_D + cy) * GRID_D + cx)) * CHP + oc * 8;
    }

    uint4 cv[4];
    #pragma unroll
    for (int c = 0; c < 4; ++c)
        cv[c] = *reinterpret_cast<const uint4*>(&grid[idx4[c]]);

    float acc[8] = {0.f, 0.f, 0.f, 0.f, 0.f, 0.f, 0.f, 0.f};
    #pragma unroll
    for (int c = 0; c < 4; ++c) {
        const unsigned u[4] = {cv[c].x, cv[c].y, cv[c].z, cv[c].w};
        #pragma unroll
        for (int kk = 0; kk < 4; ++kk) {
            const half2  h2 = *reinterpret_cast<const half2*>(&u[kk]);
            const float2 f2 = __half22float2(h2);
            acc[kk * 2 + 0] = fmaf(w4[c], f2.x, acc[kk * 2 + 0]);
            acc[kk * 2 + 1] = fmaf(w4[c], f2.y, acc[kk * 2 + 1]);
        }
    }

    // combine dx=0 and dx=1 partial sums (lanes differ in bit 1 of q)
    #pragma unroll
    for (int k = 0; k < 8; ++k)
        acc[k] += __shfl_xor_sync(0xffffffff, acc[k], 2);

    // each lane stores one float4: channels oc*8 + xs*4 .. +3
    const float4 st = xs ? make_float4(acc[4], acc[5], acc[6], acc[7])
                         : make_float4(acc[0], acc[1], acc[2], acc[3]);
    float* op = out + (size_t)p * CH + pass * CHP + oc * 8 + xs * 4;
    __stcs(reinterpret_cast<float4*>(op), st);
}

extern "C" void kernel_launch(void* const* d_in, const int* in_sizes, int n_in,
                              void* d_out, int out_size) {
    const float* x       = (const float*)d_in[0];   // (N_POINTS, 3)
    const float* feature = (const float*)d_in[1];   // (32, 128, 128, 128)
    float*       out     = (float*)d_out;           // (N_POINTS, 32)

    const int tblocks = NVOX / 256;
    const int gblocks = (N_POINTS * 4) / 256;        // 4M threads, divides exactly

    // sequential, cache-friendly order (R8): gather runs on a warm half-grid
    transpose_half<<<tblocks, 256>>>(feature, 0);
    gather_half<<<gblocks, 256>>>(x, out, 0);

    transpose_half<<<tblocks, 256>>>(feature, 1);
    gather_half<<<gblocks, 256>>>(x, out, 1);
}